// round 1
// baseline (speedup 1.0000x reference)
#include <cuda_runtime.h>
#include <cstdint>

typedef unsigned long long u64;

// Packed fp32x2 FMA (Blackwell PTX-only; doubles FFMA throughput vs 3-reg FFMA)
#define FMA2(acc, a, b) asm("fma.rn.f32x2 %0, %1, %2, %0;" : "+l"(acc) : "l"(a), "l"(b))
#define PACK2(d, s)     asm("mov.b64 %0, {%1, %1};" : "=l"(d) : "f"(s))
#define UNPACK2(lo, hi, s) asm("mov.b64 {%0, %1}, %2;" : "=f"(lo), "=f"(hi) : "l"(s))

constexpr int D       = 512;
constexpr int NCODES  = 1024;
constexpr long long NBT = 32768;             // 16 * 2048 rows

// Output packing: (z_st [32768,512], loss [1], dist [32768,1024], idx [32768]) as float32
constexpr long long Z_OFF    = 0;
constexpr long long LOSS_OFF = 16777216;
constexpr long long DIST_OFF = 16777217;
constexpr long long IDX_OFF  = 50331649;

constexpr int BM = 128, BN = 128, BK = 32, SDIM = 132;   // SDIM pads smem rows

__device__ double g_loss_acc;
__device__ float  g_e2[NCODES];

// ---------------------------------------------------------------------------
// prep: zero loss accumulator, precompute ||e_n||^2
// ---------------------------------------------------------------------------
__global__ void prep_kernel(const float* __restrict__ emb) {
    int gw   = (blockIdx.x * blockDim.x + threadIdx.x) >> 5;
    int lane = threadIdx.x & 31;
    if (gw == 0 && lane == 0) g_loss_acc = 0.0;
    if (gw < NCODES) {
        const float* row = emb + (long long)gw * D;
        float s = 0.f;
        #pragma unroll
        for (int d = lane; d < D; d += 32) { float v = row[d]; s += v * v; }
        #pragma unroll
        for (int o = 16; o; o >>= 1) s += __shfl_xor_sync(0xffffffffu, s, o);
        if (lane == 0) g_e2[gw] = s;
    }
}

// ---------------------------------------------------------------------------
// main: per block of 128 rows — dist (all 1024 codes), argmin, gather, loss
// ---------------------------------------------------------------------------
__global__ void __launch_bounds__(256) vq_main(const float* __restrict__ resid,
                                               const float* __restrict__ emb,
                                               float* __restrict__ out) {
    __shared__ float Rs[BK * SDIM];
    __shared__ float Es[BK * SDIM];
    __shared__ float e2sh[NCODES];
    __shared__ float z2s[BM];
    __shared__ int   sidx[BM];
    __shared__ float wsum[8];

    const int tid = threadIdx.x;
    const int tx  = tid & 15;          // N direction (8 cols each)
    const int ty  = tid >> 4;          // M direction (8 rows each)
    const long long row0 = (long long)blockIdx.x * BM;

    // cache ||e||^2 in smem
    for (int i = tid; i < NCODES; i += 256) e2sh[i] = g_e2[i];

    // ||r||^2 per row: warp per 16 rows
    {
        int w = tid >> 5, lane = tid & 31;
        for (int rr = 0; rr < 16; ++rr) {
            int r = w * 16 + rr;
            const float* rp = resid + (row0 + r) * D;
            float s = 0.f;
            #pragma unroll
            for (int d = lane; d < D; d += 32) { float v = rp[d]; s += v * v; }
            #pragma unroll
            for (int o = 16; o; o >>= 1) s += __shfl_xor_sync(0xffffffffu, s, o);
            if (lane == 0) z2s[r] = s;
        }
    }

    float minv[8];
    int   mini[8];
    #pragma unroll
    for (int r = 0; r < 8; ++r) { minv[r] = 3.4e38f; mini[r] = 0; }

    // fill mapping: lanes cover 32 consecutive rows (conflict-free STS), threads
    // cover full 128-byte lines in K via L1
    const int fm = (tid & 31) | ((tid >> 6) << 5);   // 0..127
    const int fk = ((tid >> 5) & 1) * 16;            // 0 or 16

    for (int nc = 0; nc < NCODES / BN; ++nc) {
        u64 acc[8][4];
        #pragma unroll
        for (int r = 0; r < 8; ++r)
            #pragma unroll
            for (int j = 0; j < 4; ++j) acc[r][j] = 0ull;

        for (int kc = 0; kc < D / BK; ++kc) {
            const float* rsrc = resid + (row0 + fm) * D + kc * BK + fk;
            const float* esrc = emb + (long long)(nc * BN + fm) * D + kc * BK + fk;
            #pragma unroll
            for (int ii = 0; ii < 4; ++ii) {
                float4 v = *(const float4*)(rsrc + ii * 4);
                int kk = fk + ii * 4;
                Rs[(kk + 0) * SDIM + fm] = v.x;
                Rs[(kk + 1) * SDIM + fm] = v.y;
                Rs[(kk + 2) * SDIM + fm] = v.z;
                Rs[(kk + 3) * SDIM + fm] = v.w;
                float4 e = *(const float4*)(esrc + ii * 4);
                Es[(kk + 0) * SDIM + fm] = e.x;
                Es[(kk + 1) * SDIM + fm] = e.y;
                Es[(kk + 2) * SDIM + fm] = e.z;
                Es[(kk + 3) * SDIM + fm] = e.w;
            }
            __syncthreads();

            #pragma unroll 8
            for (int k = 0; k < BK; ++k) {
                const float4 a0 = *(const float4*)&Rs[k * SDIM + ty * 8];
                const float4 a1 = *(const float4*)&Rs[k * SDIM + ty * 8 + 4];
                const ulonglong2 b01 = *(const ulonglong2*)&Es[k * SDIM + tx * 8];
                const ulonglong2 b23 = *(const ulonglong2*)&Es[k * SDIM + tx * 8 + 4];
                u64 av[8];
                PACK2(av[0], a0.x); PACK2(av[1], a0.y); PACK2(av[2], a0.z); PACK2(av[3], a0.w);
                PACK2(av[4], a1.x); PACK2(av[5], a1.y); PACK2(av[6], a1.z); PACK2(av[7], a1.w);
                #pragma unroll
                for (int r = 0; r < 8; ++r) {
                    FMA2(acc[r][0], av[r], b01.x);
                    FMA2(acc[r][1], av[r], b01.y);
                    FMA2(acc[r][2], av[r], b23.x);
                    FMA2(acc[r][3], av[r], b23.y);
                }
            }
            __syncthreads();
        }

        // epilogue for this n-chunk: dist = z2 + e2 - 2*dot, write + running argmin
        #pragma unroll
        for (int r = 0; r < 8; ++r) {
            const int lrow = ty * 8 + r;
            const float z2 = z2s[lrow];
            float dv[8];
            #pragma unroll
            for (int j = 0; j < 4; ++j) {
                float lo, hi;
                UNPACK2(lo, hi, acc[r][j]);
                int c = nc * BN + tx * 8 + j * 2;
                dv[j * 2]     = z2 + e2sh[c]     - 2.f * lo;
                dv[j * 2 + 1] = z2 + e2sh[c + 1] - 2.f * hi;
            }
            #pragma unroll
            for (int j = 0; j < 8; ++j) {
                int c = nc * BN + tx * 8 + j;
                float v = dv[j];
                if (v < minv[r] || (v == minv[r] && c < mini[r])) { minv[r] = v; mini[r] = c; }
            }
            // dist section starts at odd float offset -> scalar stores (still contiguous)
            float* dst = &out[DIST_OFF + (row0 + lrow) * NCODES + nc * BN + tx * 8];
            #pragma unroll
            for (int j = 0; j < 8; ++j) dst[j] = dv[j];
        }
    }

    // cross-thread argmin reduce: 16 threads (tx) share each row
    __syncthreads();
    float* rv = Rs;            // reuse: [128][17]
    int*   ri = (int*)Es;      // reuse: [128][17]
    #pragma unroll
    for (int r = 0; r < 8; ++r) {
        rv[(ty * 8 + r) * 17 + tx] = minv[r];
        ri[(ty * 8 + r) * 17 + tx] = mini[r];
    }
    __syncthreads();
    if (tid < BM) {
        float bv = rv[tid * 17];
        int   bi = ri[tid * 17];
        #pragma unroll
        for (int t = 1; t < 16; ++t) {
            float v = rv[tid * 17 + t];
            int   i = ri[tid * 17 + t];
            if (v < bv || (v == bv && i < bi)) { bv = v; bi = i; }
        }
        sidx[tid] = bi;
        out[IDX_OFF + row0 + tid] = (float)bi;
    }
    __syncthreads();

    // z_st = emb[idx] gather + loss partial sum
    float lsum = 0.f;
    for (int base = tid * 4; base < BM * D; base += 256 * 4) {
        int r = base >> 9;
        int d = base & (D - 1);
        int ci = sidx[r];
        float4 q  = *(const float4*)&emb[(long long)ci * D + d];
        long long g = (row0 + r) * D + d;
        float4 rr = *(const float4*)&resid[g];
        *(float4*)&out[Z_OFF + g] = q;
        float d0 = q.x - rr.x, d1 = q.y - rr.y, d2 = q.z - rr.z, d3 = q.w - rr.w;
        lsum += d0 * d0 + d1 * d1 + d2 * d2 + d3 * d3;
    }
    #pragma unroll
    for (int o = 16; o; o >>= 1) lsum += __shfl_xor_sync(0xffffffffu, lsum, o);
    if ((tid & 31) == 0) wsum[tid >> 5] = lsum;
    __syncthreads();
    if (tid == 0) {
        float s = 0.f;
        #pragma unroll
        for (int w = 0; w < 8; ++w) s += wsum[w];
        atomicAdd(&g_loss_acc, (double)s);
    }
}

// ---------------------------------------------------------------------------
// finalize: loss = beta*commit + codebook = 1.25 * mean((z_q - r)^2)
// ---------------------------------------------------------------------------
__global__ void finalize_kernel(float* __restrict__ out) {
    out[LOSS_OFF] = (float)(1.25 * g_loss_acc / 16777216.0);
}

extern "C" void kernel_launch(void* const* d_in, const int* in_sizes, int n_in,
                              void* d_out, int out_size) {
    const float* resid = (const float*)d_in[0];
    const float* emb   = (const float*)d_in[1];
    // defensive: inputs should be (residual[16M], emb[512K]); swap if reversed
    if (n_in >= 2 && in_sizes[0] == 524288 && in_sizes[1] == 16777216) {
        const float* t = resid; resid = emb; emb = t;
    }
    float* out = (float*)d_out;

    prep_kernel<<<128, 256>>>(emb);
    vq_main<<<(int)(NBT / BM), 256>>>(resid, emb, out);
    finalize_kernel<<<1, 1>>>(out);
}

// round 4
// speedup vs baseline: 2.3805x; 2.3805x over previous
#include <cuda_runtime.h>
#include <cuda_bf16.h>
#include <cstdint>

typedef unsigned long long u64;
typedef unsigned int u32;

// ---------------- problem constants ----------------
constexpr int D = 512, NCODES = 1024;
constexpr long long NBT = 32768;
constexpr long long Z_OFF = 0, LOSS_OFF = 16777216, DIST_OFF = 16777217, IDX_OFF = 50331649;

constexpr int BM = 128;      // rows per CTA
constexpr int BN = 128;      // codes per n-chunk
constexpr int BK = 64;       // bf16 k per stage (= 128B rows, SW128)

// ---------------- device scratch ----------------
__device__ __align__(128) __nv_bfloat16 g_Rhi[NBT * D];
__device__ __align__(128) __nv_bfloat16 g_Rlo[NBT * D];
__device__ __align__(128) __nv_bfloat16 g_Ehi[NCODES * D];
__device__ __align__(128) __nv_bfloat16 g_Elo[NCODES * D];
__device__ float  g_z2[NBT];
__device__ float  g_e2[NCODES];
__device__ double g_loss_acc;

// ---------------- PTX helpers (sm_80-era only: safe for compute_103) -------
__device__ __forceinline__ u32 smem_u32(const void* p) {
    u32 a;
    asm("{ .reg .u64 t; cvta.to.shared.u64 t, %1; cvt.u32.u64 %0, t; }" : "=r"(a) : "l"(p));
    return a;
}
#define SW128(o) ((o) ^ (((o) >> 3) & 0x70))

#define CP16(saddr, gptr) \
    asm volatile("cp.async.cg.shared.global [%0], [%1], 16;" :: "r"(saddr), "l"(gptr))
#define CP_COMMIT() asm volatile("cp.async.commit_group;" ::: "memory")
#define CP_WAIT1()  asm volatile("cp.async.wait_group 1;" ::: "memory")
#define CP_WAIT0()  asm volatile("cp.async.wait_group 0;" ::: "memory")

__device__ __forceinline__ void ldsm4(u32* r, u32 addr) {
    asm volatile("ldmatrix.sync.aligned.m8n8.x4.shared.b16 {%0,%1,%2,%3}, [%4];"
                 : "=r"(r[0]), "=r"(r[1]), "=r"(r[2]), "=r"(r[3]) : "r"(addr));
}
__device__ __forceinline__ void mma16816(float* c, const u32* a, u32 b0, u32 b1) {
    asm volatile("mma.sync.aligned.m16n8k16.row.col.f32.bf16.bf16.f32 "
                 "{%0,%1,%2,%3}, {%4,%5,%6,%7}, {%8,%9}, {%0,%1,%2,%3};"
                 : "+f"(c[0]), "+f"(c[1]), "+f"(c[2]), "+f"(c[3])
                 : "r"(a[0]), "r"(a[1]), "r"(a[2]), "r"(a[3]), "r"(b0), "r"(b1));
}

// ---------------- prep: split fp32 -> bf16 hi/lo + row norms ----------------
__global__ void prep_r(const float* __restrict__ src) {
    __shared__ float part[8];
    long long row = blockIdx.x * 2 + (threadIdx.x >> 7);
    int t = threadIdx.x & 127;
    float4 v = *(const float4*)(src + row * D + t * 4);
    __nv_bfloat16 hx = __float2bfloat16(v.x), hy = __float2bfloat16(v.y);
    __nv_bfloat16 hz = __float2bfloat16(v.z), hw = __float2bfloat16(v.w);
    __nv_bfloat16 lx = __float2bfloat16(v.x - __bfloat162float(hx));
    __nv_bfloat16 ly = __float2bfloat16(v.y - __bfloat162float(hy));
    __nv_bfloat16 lz = __float2bfloat16(v.z - __bfloat162float(hz));
    __nv_bfloat16 lw = __float2bfloat16(v.w - __bfloat162float(hw));
    long long o = row * D + t * 4;
    ((__nv_bfloat162*)(g_Rhi + o))[0] = __nv_bfloat162{hx, hy};
    ((__nv_bfloat162*)(g_Rhi + o))[1] = __nv_bfloat162{hz, hw};
    ((__nv_bfloat162*)(g_Rlo + o))[0] = __nv_bfloat162{lx, ly};
    ((__nv_bfloat162*)(g_Rlo + o))[1] = __nv_bfloat162{lz, lw};
    float s = v.x * v.x + v.y * v.y + v.z * v.z + v.w * v.w;
    #pragma unroll
    for (int k = 16; k; k >>= 1) s += __shfl_xor_sync(0xffffffffu, s, k);
    if ((threadIdx.x & 31) == 0) part[threadIdx.x >> 5] = s;
    __syncthreads();
    if (t == 0) {
        int b = (threadIdx.x >> 7) * 4;
        g_z2[row] = part[b] + part[b + 1] + part[b + 2] + part[b + 3];
    }
}

__global__ void prep_e(const float* __restrict__ src) {
    __shared__ float part[8];
    if (blockIdx.x == 0 && threadIdx.x == 0) g_loss_acc = 0.0;
    long long row = blockIdx.x * 2 + (threadIdx.x >> 7);
    int t = threadIdx.x & 127;
    float4 v = *(const float4*)(src + row * D + t * 4);
    __nv_bfloat16 hx = __float2bfloat16(v.x), hy = __float2bfloat16(v.y);
    __nv_bfloat16 hz = __float2bfloat16(v.z), hw = __float2bfloat16(v.w);
    __nv_bfloat16 lx = __float2bfloat16(v.x - __bfloat162float(hx));
    __nv_bfloat16 ly = __float2bfloat16(v.y - __bfloat162float(hy));
    __nv_bfloat16 lz = __float2bfloat16(v.z - __bfloat162float(hz));
    __nv_bfloat16 lw = __float2bfloat16(v.w - __bfloat162float(hw));
    long long o = row * D + t * 4;
    ((__nv_bfloat162*)(g_Ehi + o))[0] = __nv_bfloat162{hx, hy};
    ((__nv_bfloat162*)(g_Ehi + o))[1] = __nv_bfloat162{hz, hw};
    ((__nv_bfloat162*)(g_Elo + o))[0] = __nv_bfloat162{lx, ly};
    ((__nv_bfloat162*)(g_Elo + o))[1] = __nv_bfloat162{lz, lw};
    float s = v.x * v.x + v.y * v.y + v.z * v.z + v.w * v.w;
    #pragma unroll
    for (int k = 16; k; k >>= 1) s += __shfl_xor_sync(0xffffffffu, s, k);
    if ((threadIdx.x & 31) == 0) part[threadIdx.x >> 5] = s;
    __syncthreads();
    if (t == 0) {
        int b = (threadIdx.x >> 7) * 4;
        g_e2[row] = part[b] + part[b + 1] + part[b + 2] + part[b + 3];
    }
}

// ---------------- main: mma.sync bf16x3 GEMM + fused VQ epilogue ------------
// stage layout: Ahi 16K | Alo 16K | Bhi 16K | Blo 16K  = 64KB, double buffered
constexpr int STAGE = 65536;
constexpr int DSMEM = 2 * STAGE;

__global__ void __launch_bounds__(256, 1) vq_main(const float* __restrict__ resid,
                                                  const float* __restrict__ emb,
                                                  float* __restrict__ out) {
    extern __shared__ char dsm[];
    __shared__ float z2s[BM];
    __shared__ float e2sh[NCODES];
    __shared__ float bestV[BM][2];
    __shared__ int   bestI[BM][2];
    __shared__ int   sidx[BM];
    __shared__ float wsum[8];

    const int tid = threadIdx.x, wid = tid >> 5, lane = tid & 31;
    const int warp_m = wid & 3, warp_n = wid >> 2;
    const long long row0 = (long long)blockIdx.x * BM;
    const u32 sbase = smem_u32(dsm);

    if (tid < BM) z2s[tid] = g_z2[row0 + tid];
    for (int i = tid; i < NCODES; i += 256) e2sh[i] = g_e2[i];

    // per-lane running argmin: 4 row-slots (mt*2 + upper/lower)
    float bv[4]; int bi[4];
    #pragma unroll
    for (int s = 0; s < 4; ++s) { bv[s] = 3.4e38f; bi[s] = 0; }

    // gmem load mapping: idx = tid + i*256 -> row = idx>>3, chunk = idx&7 (16B)
    const int lrow = tid >> 3, lchk = tid & 7;

    for (int nc = 0; nc < NCODES / BN; ++nc) {
        float acc[2][8][4];
        #pragma unroll
        for (int mt = 0; mt < 2; ++mt)
            #pragma unroll
            for (int nt = 0; nt < 8; ++nt)
                #pragma unroll
                for (int q = 0; q < 4; ++q) acc[mt][nt][q] = 0.f;

        // ---- prologue: stage 0 ----
        {
            u32 st = sbase;
            #pragma unroll
            for (int i = 0; i < 4; ++i) {
                int r = lrow + i * 32;
                u32 off = SW128((u32)(r * 128 + lchk * 16));
                long long ga = (row0 + r) * D + lchk * 8;
                long long gb = (long long)(nc * BN + r) * D + lchk * 8;
                CP16(st + off,         g_Rhi + ga);
                CP16(st + 16384 + off, g_Rlo + ga);
                CP16(st + 32768 + off, g_Ehi + gb);
                CP16(st + 49152 + off, g_Elo + gb);
            }
            CP_COMMIT();
        }

        for (int kc = 0; kc < D / BK; ++kc) {
            const int buf = kc & 1;
            if (kc < D / BK - 1) {
                u32 st = sbase + (buf ^ 1) * STAGE;
                const int kn = (kc + 1) * BK;
                #pragma unroll
                for (int i = 0; i < 4; ++i) {
                    int r = lrow + i * 32;
                    u32 off = SW128((u32)(r * 128 + lchk * 16));
                    long long ga = (row0 + r) * D + kn + lchk * 8;
                    long long gb = (long long)(nc * BN + r) * D + kn + lchk * 8;
                    CP16(st + off,         g_Rhi + ga);
                    CP16(st + 16384 + off, g_Rlo + ga);
                    CP16(st + 32768 + off, g_Ehi + gb);
                    CP16(st + 49152 + off, g_Elo + gb);
                }
                CP_COMMIT();
                CP_WAIT1();
            } else {
                CP_WAIT0();
            }
            __syncthreads();

            const u32 Ah = sbase + buf * STAGE;
            const u32 Al = Ah + 16384, Bh = Ah + 32768, Bl = Ah + 49152;

            #pragma unroll
            for (int ks = 0; ks < 4; ++ks) {
                const u32 kb = (u32)((ks * 2 + (lane >> 4)) << 4);
                u32 a_hi[2][4], a_lo[2][4];
                #pragma unroll
                for (int mt = 0; mt < 2; ++mt) {
                    u32 off = SW128((u32)((warp_m * 32 + mt * 16 + (lane & 15)) << 7) + kb);
                    ldsm4(a_hi[mt], Ah + off);
                    ldsm4(a_lo[mt], Al + off);
                }
                // B is stored [n][k] (k contiguous) == "col" operand layout:
                // plain (non-trans) ldmatrix yields the correct b-fragment.
                u32 b_hi[4][4], b_lo[4][4];
                #pragma unroll
                for (int ng = 0; ng < 4; ++ng) {
                    u32 off = SW128((u32)((warp_n * 64 + ng * 16 + (lane & 15)) << 7) + kb);
                    ldsm4(b_hi[ng], Bh + off);
                    ldsm4(b_lo[ng], Bl + off);
                }
                #pragma unroll
                for (int mt = 0; mt < 2; ++mt)
                    #pragma unroll
                    for (int ng = 0; ng < 4; ++ng)
                        #pragma unroll
                        for (int sb = 0; sb < 2; ++sb) {
                            float* c = acc[mt][ng * 2 + sb];
                            mma16816(c, a_hi[mt], b_hi[ng][sb], b_hi[ng][sb + 2]); // hh
                            mma16816(c, a_hi[mt], b_lo[ng][sb], b_lo[ng][sb + 2]); // hl
                            mma16816(c, a_lo[mt], b_hi[ng][sb], b_hi[ng][sb + 2]); // lh
                        }
            }
            __syncthreads();
        }

        // ---- epilogue: dist, argmin, store ----
        const int qr = lane >> 2, qc = lane & 3;
        #pragma unroll
        for (int mt = 0; mt < 2; ++mt) {
            const int ra = warp_m * 32 + mt * 16 + qr;   // local row (upper)
            const int rb = ra + 8;                        // local row (lower)
            const float z2a = z2s[ra], z2b = z2s[rb];
            #pragma unroll
            for (int nt = 0; nt < 8; ++nt) {
                const int col = nc * BN + warp_n * 64 + nt * 8 + qc * 2;
                const float e0 = e2sh[col], e1 = e2sh[col + 1];
                float d00 = fmaf(-2.f, acc[mt][nt][0], z2a + e0);
                float d01 = fmaf(-2.f, acc[mt][nt][1], z2a + e1);
                float d10 = fmaf(-2.f, acc[mt][nt][2], z2b + e0);
                float d11 = fmaf(-2.f, acc[mt][nt][3], z2b + e1);
                const int sa = mt * 2, sbs = mt * 2 + 1;
                if (d00 < bv[sa])  { bv[sa] = d00;  bi[sa] = col; }
                if (d01 < bv[sa])  { bv[sa] = d01;  bi[sa] = col + 1; }
                if (d10 < bv[sbs]) { bv[sbs] = d10; bi[sbs] = col; }
                if (d11 < bv[sbs]) { bv[sbs] = d11; bi[sbs] = col + 1; }
                long long oa = DIST_OFF + (row0 + ra) * 1024 + col;
                long long ob = DIST_OFF + (row0 + rb) * 1024 + col;
                out[oa] = d00; out[oa + 1] = d01;
                out[ob] = d10; out[ob + 1] = d11;
            }
        }
    }

    // ---- per-row argmin reduce (quad shfl, then across warp_n halves) ----
    #pragma unroll
    for (int s = 0; s < 4; ++s) {
        #pragma unroll
        for (int o = 1; o <= 2; o <<= 1) {
            float vv = __shfl_xor_sync(0xffffffffu, bv[s], o);
            int   ii = __shfl_xor_sync(0xffffffffu, bi[s], o);
            if (vv < bv[s] || (vv == bv[s] && ii < bi[s])) { bv[s] = vv; bi[s] = ii; }
        }
    }
    if ((lane & 3) == 0) {
        const int qr = lane >> 2;
        #pragma unroll
        for (int mt = 0; mt < 2; ++mt) {
            int ra = warp_m * 32 + mt * 16 + qr;
            bestV[ra][warp_n] = bv[mt * 2];     bestI[ra][warp_n] = bi[mt * 2];
            bestV[ra + 8][warp_n] = bv[mt * 2 + 1]; bestI[ra + 8][warp_n] = bi[mt * 2 + 1];
        }
    }
    __syncthreads();
    if (tid < BM) {
        float v0 = bestV[tid][0]; int i0 = bestI[tid][0];
        float v1 = bestV[tid][1]; int i1 = bestI[tid][1];
        bool t1 = (v1 < v0) || (v1 == v0 && i1 < i0);
        int b = t1 ? i1 : i0;
        sidx[tid] = b;
        out[IDX_OFF + row0 + tid] = (float)b;
    }
    __syncthreads();

    // ---- z_st gather + loss partial (exact fp32 from original inputs) ----
    float lsum = 0.f;
    for (int base = tid * 4; base < BM * D; base += 256 * 4) {
        int r = base >> 9;
        int d = base & (D - 1);
        int ci = sidx[r];
        float4 q = *(const float4*)&emb[(long long)ci * D + d];
        long long g = (row0 + r) * D + d;
        float4 rv = *(const float4*)&resid[g];
        *(float4*)&out[Z_OFF + g] = q;
        float d0 = q.x - rv.x, d1 = q.y - rv.y, d2 = q.z - rv.z, d3 = q.w - rv.w;
        lsum += d0 * d0 + d1 * d1 + d2 * d2 + d3 * d3;
    }
    #pragma unroll
    for (int o = 16; o; o >>= 1) lsum += __shfl_xor_sync(0xffffffffu, lsum, o);
    if (lane == 0) wsum[wid] = lsum;
    __syncthreads();
    if (tid == 0) {
        float s = 0.f;
        #pragma unroll
        for (int w = 0; w < 8; ++w) s += wsum[w];
        atomicAdd(&g_loss_acc, (double)s);
    }
}

__global__ void finalize_kernel(float* __restrict__ out) {
    out[LOSS_OFF] = (float)(1.25 * g_loss_acc / 16777216.0);
}

extern "C" void kernel_launch(void* const* d_in, const int* in_sizes, int n_in,
                              void* d_out, int out_size) {
    const float* resid = (const float*)d_in[0];
    const float* emb   = (const float*)d_in[1];
    if (n_in >= 2 && in_sizes[0] == 524288 && in_sizes[1] == 16777216) {
        const float* t = resid; resid = emb; emb = t;
    }
    float* out = (float*)d_out;

    static int smem_set = 0;
    if (!smem_set) {
        cudaFuncSetAttribute(vq_main, cudaFuncAttributeMaxDynamicSharedMemorySize, DSMEM);
        smem_set = 1;
    }

    prep_r<<<16384, 256>>>(resid);
    prep_e<<<512, 256>>>(emb);
    vq_main<<<256, 256, DSMEM>>>(resid, emb, out);
    finalize_kernel<<<1, 1>>>(out);
}

// round 5
// speedup vs baseline: 2.4291x; 1.0204x over previous
#include <cuda_runtime.h>
#include <cuda_bf16.h>
#include <cstdint>

typedef unsigned long long u64;
typedef unsigned int u32;

// ---------------- problem constants ----------------
constexpr int D = 512, NCODES = 1024;
constexpr long long NBT = 32768;
constexpr long long Z_OFF = 0, LOSS_OFF = 16777216, DIST_OFF = 16777217, IDX_OFF = 50331649;

constexpr int BM = 128;      // rows per CTA
constexpr int BN = 128;      // codes per n-chunk
constexpr int BK = 32;       // bf16 k per stage; row = [hi 64B | lo 64B] = 128B

// ---------------- device scratch ----------------
__device__ __align__(128) __nv_bfloat16 g_Rhi[NBT * D];
__device__ __align__(128) __nv_bfloat16 g_Rlo[NBT * D];
__device__ __align__(128) __nv_bfloat16 g_Ehi[NCODES * D];
__device__ __align__(128) __nv_bfloat16 g_Elo[NCODES * D];
__device__ float  g_z2[NBT];
__device__ float  g_e2[NCODES];
__device__ double g_loss_acc;

// ---------------- PTX helpers (sm_80-era only: safe for compute_103) -------
__device__ __forceinline__ u32 smem_u32(const void* p) {
    u32 a;
    asm("{ .reg .u64 t; cvta.to.shared.u64 t, %1; cvt.u32.u64 %0, t; }" : "=r"(a) : "l"(p));
    return a;
}
#define SW128(o) ((o) ^ (((o) >> 3) & 0x70))

#define CP16(saddr, gptr) \
    asm volatile("cp.async.cg.shared.global [%0], [%1], 16;" :: "r"(saddr), "l"(gptr))
#define CP_COMMIT() asm volatile("cp.async.commit_group;" ::: "memory")
#define CP_WAIT2()  asm volatile("cp.async.wait_group 2;" ::: "memory")

__device__ __forceinline__ void ldsm4(u32* r, u32 addr) {
    asm volatile("ldmatrix.sync.aligned.m8n8.x4.shared.b16 {%0,%1,%2,%3}, [%4];"
                 : "=r"(r[0]), "=r"(r[1]), "=r"(r[2]), "=r"(r[3]) : "r"(addr));
}
__device__ __forceinline__ void mma16816(float* c, const u32* a, u32 b0, u32 b1) {
    asm volatile("mma.sync.aligned.m16n8k16.row.col.f32.bf16.bf16.f32 "
                 "{%0,%1,%2,%3}, {%4,%5,%6,%7}, {%8,%9}, {%0,%1,%2,%3};"
                 : "+f"(c[0]), "+f"(c[1]), "+f"(c[2]), "+f"(c[3])
                 : "r"(a[0]), "r"(a[1]), "r"(a[2]), "r"(a[3]), "r"(b0), "r"(b1));
}

// ---------------- prep: split fp32 -> bf16 hi/lo + row norms ----------------
__global__ void prep_r(const float* __restrict__ src) {
    __shared__ float part[8];
    long long row = blockIdx.x * 2 + (threadIdx.x >> 7);
    int t = threadIdx.x & 127;
    float4 v = *(const float4*)(src + row * D + t * 4);
    __nv_bfloat16 hx = __float2bfloat16(v.x), hy = __float2bfloat16(v.y);
    __nv_bfloat16 hz = __float2bfloat16(v.z), hw = __float2bfloat16(v.w);
    __nv_bfloat16 lx = __float2bfloat16(v.x - __bfloat162float(hx));
    __nv_bfloat16 ly = __float2bfloat16(v.y - __bfloat162float(hy));
    __nv_bfloat16 lz = __float2bfloat16(v.z - __bfloat162float(hz));
    __nv_bfloat16 lw = __float2bfloat16(v.w - __bfloat162float(hw));
    long long o = row * D + t * 4;
    ((__nv_bfloat162*)(g_Rhi + o))[0] = __nv_bfloat162{hx, hy};
    ((__nv_bfloat162*)(g_Rhi + o))[1] = __nv_bfloat162{hz, hw};
    ((__nv_bfloat162*)(g_Rlo + o))[0] = __nv_bfloat162{lx, ly};
    ((__nv_bfloat162*)(g_Rlo + o))[1] = __nv_bfloat162{lz, lw};
    float s = v.x * v.x + v.y * v.y + v.z * v.z + v.w * v.w;
    #pragma unroll
    for (int k = 16; k; k >>= 1) s += __shfl_xor_sync(0xffffffffu, s, k);
    if ((threadIdx.x & 31) == 0) part[threadIdx.x >> 5] = s;
    __syncthreads();
    if (t == 0) {
        int b = (threadIdx.x >> 7) * 4;
        g_z2[row] = part[b] + part[b + 1] + part[b + 2] + part[b + 3];
    }
}

__global__ void prep_e(const float* __restrict__ src) {
    __shared__ float part[8];
    if (blockIdx.x == 0 && threadIdx.x == 0) g_loss_acc = 0.0;
    long long row = blockIdx.x * 2 + (threadIdx.x >> 7);
    int t = threadIdx.x & 127;
    float4 v = *(const float4*)(src + row * D + t * 4);
    __nv_bfloat16 hx = __float2bfloat16(v.x), hy = __float2bfloat16(v.y);
    __nv_bfloat16 hz = __float2bfloat16(v.z), hw = __float2bfloat16(v.w);
    __nv_bfloat16 lx = __float2bfloat16(v.x - __bfloat162float(hx));
    __nv_bfloat16 ly = __float2bfloat16(v.y - __bfloat162float(hy));
    __nv_bfloat16 lz = __float2bfloat16(v.z - __bfloat162float(hz));
    __nv_bfloat16 lw = __float2bfloat16(v.w - __bfloat162float(hw));
    long long o = row * D + t * 4;
    ((__nv_bfloat162*)(g_Ehi + o))[0] = __nv_bfloat162{hx, hy};
    ((__nv_bfloat162*)(g_Ehi + o))[1] = __nv_bfloat162{hz, hw};
    ((__nv_bfloat162*)(g_Elo + o))[0] = __nv_bfloat162{lx, ly};
    ((__nv_bfloat162*)(g_Elo + o))[1] = __nv_bfloat162{lz, lw};
    float s = v.x * v.x + v.y * v.y + v.z * v.z + v.w * v.w;
    #pragma unroll
    for (int k = 16; k; k >>= 1) s += __shfl_xor_sync(0xffffffffu, s, k);
    if ((threadIdx.x & 31) == 0) part[threadIdx.x >> 5] = s;
    __syncthreads();
    if (t == 0) {
        int b = (threadIdx.x >> 7) * 4;
        g_e2[row] = part[b] + part[b + 1] + part[b + 2] + part[b + 3];
    }
}

// ---------------- main: mma.sync bf16x3 GEMM + fused VQ epilogue ------------
// stage: A (128 rows x [32k hi | 32k lo] = 128B) 16KB | B same 16KB = 32KB
// 3-stage ring = 96KB dynamic smem; 2 CTAs / SM.
constexpr int STAGE = 32768;
constexpr int DSMEM = 3 * STAGE;
constexpr int KC_PER_NC = D / BK;          // 16
constexpr int ITERS = (NCODES / BN) * KC_PER_NC;  // 128

__global__ void __launch_bounds__(256, 2) vq_main(const float* __restrict__ resid,
                                                  const float* __restrict__ emb,
                                                  float* __restrict__ out) {
    extern __shared__ char dsm[];
    __shared__ float z2s[BM];
    __shared__ float e2sh[NCODES];
    __shared__ float bestV[BM][2];
    __shared__ int   bestI[BM][2];
    __shared__ int   sidx[BM];
    __shared__ float wsum[8];

    const int tid = threadIdx.x, wid = tid >> 5, lane = tid & 31;
    const int warp_m = wid & 3, warp_n = wid >> 2;
    const long long row0 = (long long)blockIdx.x * BM;
    const u32 sbase = smem_u32(dsm);

    if (tid < BM) z2s[tid] = g_z2[row0 + tid];
    for (int i = tid; i < NCODES; i += 256) e2sh[i] = g_e2[i];

    float bv[4]; int bi[4];
    #pragma unroll
    for (int s = 0; s < 4; ++s) { bv[s] = 3.4e38f; bi[s] = 0; }

    // load mapping (constant per thread): sub = tid&7 selects hi(0-3)/lo(4-7)
    // 16B chunk within the packed 128B row; rows advance with i.
    const int sub  = tid & 7;
    const int rbase = tid >> 3;                    // 0..31
    const bool is_hi = sub < 4;
    const int koff8 = (sub & 3) * 8;               // bf16 elements within 32-k chunk
    const u32 dsub = (u32)(sub * 16);              // byte offset in 128B row

    const __nv_bfloat16* Asrc = is_hi ? g_Rhi : g_Rlo;
    const __nv_bfloat16* Bsrc = is_hi ? g_Ehi : g_Elo;

    // ---- pipeline prologue: stages for it=0,1 ----
    #pragma unroll
    for (int p = 0; p < 2; ++p) {
        const int nc2 = p >> 4, kc2 = p & 15;
        u32 st = sbase + (u32)((p % 3) * STAGE);
        #pragma unroll
        for (int i = 0; i < 4; ++i) {
            int r = rbase + i * 32;
            u32 off = SW128((u32)(r * 128) + dsub);
            CP16(st + off,         Asrc + (row0 + r) * D + kc2 * BK + koff8);
            CP16(st + 16384 + off, Bsrc + (long long)(nc2 * BN + r) * D + kc2 * BK + koff8);
        }
        CP_COMMIT();
    }

    float acc[2][8][4];

    for (int it = 0; it < ITERS; ++it) {
        const int nc = it >> 4, kc = it & 15;
        if (kc == 0) {
            #pragma unroll
            for (int mt = 0; mt < 2; ++mt)
                #pragma unroll
                for (int nt = 0; nt < 8; ++nt)
                    #pragma unroll
                    for (int q = 0; q < 4; ++q) acc[mt][nt][q] = 0.f;
        }
        // prefetch it+2
        if (it + 2 < ITERS) {
            const int j = it + 2, nc2 = j >> 4, kc2 = j & 15;
            u32 st = sbase + (u32)((j % 3) * STAGE);
            #pragma unroll
            for (int i = 0; i < 4; ++i) {
                int r = rbase + i * 32;
                u32 off = SW128((u32)(r * 128) + dsub);
                CP16(st + off,         Asrc + (row0 + r) * D + kc2 * BK + koff8);
                CP16(st + 16384 + off, Bsrc + (long long)(nc2 * BN + r) * D + kc2 * BK + koff8);
            }
        }
        CP_COMMIT();
        CP_WAIT2();
        __syncthreads();

        const u32 Ab = sbase + (u32)((it % 3) * STAGE);
        const u32 Bb = Ab + 16384;

        #pragma unroll
        for (int ks = 0; ks < 2; ++ks) {
            const u32 kb = (u32)(ks * 32 + ((lane >> 4) << 4));  // hi chunk bytes
            u32 a_hi[2][4], a_lo[2][4];
            #pragma unroll
            for (int mt = 0; mt < 2; ++mt) {
                u32 rowoff = (u32)((warp_m * 32 + mt * 16 + (lane & 15)) << 7);
                ldsm4(a_hi[mt], Ab + SW128(rowoff + kb));
                ldsm4(a_lo[mt], Ab + SW128(rowoff + kb + 64));
            }
            u32 b_hi[4][4], b_lo[4][4];
            #pragma unroll
            for (int ng = 0; ng < 4; ++ng) {
                u32 rowoff = (u32)((warp_n * 64 + ng * 16 + (lane & 15)) << 7);
                ldsm4(b_hi[ng], Bb + SW128(rowoff + kb));
                ldsm4(b_lo[ng], Bb + SW128(rowoff + kb + 64));
            }
            #pragma unroll
            for (int mt = 0; mt < 2; ++mt)
                #pragma unroll
                for (int ng = 0; ng < 4; ++ng)
                    #pragma unroll
                    for (int sb = 0; sb < 2; ++sb) {
                        float* c = acc[mt][ng * 2 + sb];
                        mma16816(c, a_hi[mt], b_hi[ng][sb], b_hi[ng][sb + 2]); // hh
                        mma16816(c, a_hi[mt], b_lo[ng][sb], b_lo[ng][sb + 2]); // hl
                        mma16816(c, a_lo[mt], b_hi[ng][sb], b_hi[ng][sb + 2]); // lh
                    }
        }

        if (kc == 15) {
            // ---- epilogue: dist, argmin, store (regs + read-only smem) ----
            const int qr = lane >> 2, qc = lane & 3;
            #pragma unroll
            for (int mt = 0; mt < 2; ++mt) {
                const int ra = warp_m * 32 + mt * 16 + qr;
                const int rb = ra + 8;
                const float z2a = z2s[ra], z2b = z2s[rb];
                #pragma unroll
                for (int nt = 0; nt < 8; ++nt) {
                    const int col = nc * BN + warp_n * 64 + nt * 8 + qc * 2;
                    const float e0 = e2sh[col], e1 = e2sh[col + 1];
                    float d00 = fmaf(-2.f, acc[mt][nt][0], z2a + e0);
                    float d01 = fmaf(-2.f, acc[mt][nt][1], z2a + e1);
                    float d10 = fmaf(-2.f, acc[mt][nt][2], z2b + e0);
                    float d11 = fmaf(-2.f, acc[mt][nt][3], z2b + e1);
                    const int sa = mt * 2, sbs = mt * 2 + 1;
                    if (d00 < bv[sa])  { bv[sa] = d00;  bi[sa] = col; }
                    if (d01 < bv[sa])  { bv[sa] = d01;  bi[sa] = col + 1; }
                    if (d10 < bv[sbs]) { bv[sbs] = d10; bi[sbs] = col; }
                    if (d11 < bv[sbs]) { bv[sbs] = d11; bi[sbs] = col + 1; }
                    long long oa = DIST_OFF + (row0 + ra) * 1024 + col;
                    long long ob = DIST_OFF + (row0 + rb) * 1024 + col;
                    out[oa] = d00; out[oa + 1] = d01;
                    out[ob] = d10; out[ob + 1] = d11;
                }
            }
        }
        __syncthreads();
    }

    // ---- per-row argmin reduce (quad shfl, then across warp_n halves) ----
    #pragma unroll
    for (int s = 0; s < 4; ++s) {
        #pragma unroll
        for (int o = 1; o <= 2; o <<= 1) {
            float vv = __shfl_xor_sync(0xffffffffu, bv[s], o);
            int   ii = __shfl_xor_sync(0xffffffffu, bi[s], o);
            if (vv < bv[s] || (vv == bv[s] && ii < bi[s])) { bv[s] = vv; bi[s] = ii; }
        }
    }
    if ((lane & 3) == 0) {
        const int qr = lane >> 2;
        #pragma unroll
        for (int mt = 0; mt < 2; ++mt) {
            int ra = warp_m * 32 + mt * 16 + qr;
            bestV[ra][warp_n] = bv[mt * 2];     bestI[ra][warp_n] = bi[mt * 2];
            bestV[ra + 8][warp_n] = bv[mt * 2 + 1]; bestI[ra + 8][warp_n] = bi[mt * 2 + 1];
        }
    }
    __syncthreads();
    if (tid < BM) {
        float v0 = bestV[tid][0]; int i0 = bestI[tid][0];
        float v1 = bestV[tid][1]; int i1 = bestI[tid][1];
        bool t1 = (v1 < v0) || (v1 == v0 && i1 < i0);
        int b = t1 ? i1 : i0;
        sidx[tid] = b;
        out[IDX_OFF + row0 + tid] = (float)b;
    }
    __syncthreads();

    // ---- z_st gather + loss partial (exact fp32 from original inputs) ----
    float lsum = 0.f;
    for (int base = tid * 4; base < BM * D; base += 256 * 4) {
        int r = base >> 9;
        int d = base & (D - 1);
        int ci = sidx[r];
        float4 q = *(const float4*)&emb[(long long)ci * D + d];
        long long g = (row0 + r) * D + d;
        float4 rv = *(const float4*)&resid[g];
        *(float4*)&out[Z_OFF + g] = q;
        float d0 = q.x - rv.x, d1 = q.y - rv.y, d2 = q.z - rv.z, d3 = q.w - rv.w;
        lsum += d0 * d0 + d1 * d1 + d2 * d2 + d3 * d3;
    }
    #pragma unroll
    for (int o = 16; o; o >>= 1) lsum += __shfl_xor_sync(0xffffffffu, lsum, o);
    if (lane == 0) wsum[wid] = lsum;
    __syncthreads();
    if (tid == 0) {
        float s = 0.f;
        #pragma unroll
        for (int w = 0; w < 8; ++w) s += wsum[w];
        atomicAdd(&g_loss_acc, (double)s);
    }
}

__global__ void finalize_kernel(float* __restrict__ out) {
    out[LOSS_OFF] = (float)(1.25 * g_loss_acc / 16777216.0);
}

extern "C" void kernel_launch(void* const* d_in, const int* in_sizes, int n_in,
                              void* d_out, int out_size) {
    const float* resid = (const float*)d_in[0];
    const float* emb   = (const float*)d_in[1];
    if (n_in >= 2 && in_sizes[0] == 524288 && in_sizes[1] == 16777216) {
        const float* t = resid; resid = emb; emb = t;
    }
    float* out = (float*)d_out;

    static int smem_set = 0;
    if (!smem_set) {
        cudaFuncSetAttribute(vq_main, cudaFuncAttributeMaxDynamicSharedMemorySize, DSMEM);
        smem_set = 1;
    }

    prep_r<<<16384, 256>>>(resid);
    prep_e<<<512, 256>>>(emb);
    vq_main<<<256, 256, DSMEM>>>(resid, emb, out);
    finalize_kernel<<<1, 1>>>(out);
}

// round 6
// speedup vs baseline: 2.4422x; 1.0054x over previous
#include <cuda_runtime.h>
#include <cuda_bf16.h>
#include <cstdint>

typedef unsigned long long u64;
typedef unsigned int u32;

// ---------------- problem constants ----------------
constexpr int D = 512, NCODES = 1024;
constexpr long long NBT = 32768;
constexpr long long Z_OFF = 0, LOSS_OFF = 16777216, DIST_OFF = 16777217, IDX_OFF = 50331649;

constexpr int BM = 128;      // rows per CTA
constexpr int BN = 128;      // codes per n-chunk
constexpr int BK = 32;       // bf16 k per stage; row = [hi 64B | lo 64B] = 128B

// ---------------- device scratch ----------------
__device__ __align__(128) __nv_bfloat16 g_Rhi[NBT * D];
__device__ __align__(128) __nv_bfloat16 g_Rlo[NBT * D];
__device__ __align__(128) __nv_bfloat16 g_Ehi[NCODES * D];
__device__ __align__(128) __nv_bfloat16 g_Elo[NCODES * D];
__device__ float  g_z2[NBT];
__device__ float  g_e2[NCODES];
__device__ double g_loss_acc;

// ---------------- PTX helpers (sm_80-era only: safe for compute_103) -------
__device__ __forceinline__ u32 smem_u32(const void* p) {
    u32 a;
    asm("{ .reg .u64 t; cvta.to.shared.u64 t, %1; cvt.u32.u64 %0, t; }" : "=r"(a) : "l"(p));
    return a;
}
#define SW128(o) ((o) ^ (((o) >> 3) & 0x70))

#define CP16(saddr, gptr) \
    asm volatile("cp.async.cg.shared.global [%0], [%1], 16;" :: "r"(saddr), "l"(gptr))
#define CP_COMMIT() asm volatile("cp.async.commit_group;" ::: "memory")
#define CP_WAIT2()  asm volatile("cp.async.wait_group 2;" ::: "memory")

__device__ __forceinline__ void ldsm4(u32* r, u32 addr) {
    asm volatile("ldmatrix.sync.aligned.m8n8.x4.shared.b16 {%0,%1,%2,%3}, [%4];"
                 : "=r"(r[0]), "=r"(r[1]), "=r"(r[2]), "=r"(r[3]) : "r"(addr));
}
__device__ __forceinline__ void mma16816(float* c, const u32* a, u32 b0, u32 b1) {
    asm volatile("mma.sync.aligned.m16n8k16.row.col.f32.bf16.bf16.f32 "
                 "{%0,%1,%2,%3}, {%4,%5,%6,%7}, {%8,%9}, {%0,%1,%2,%3};"
                 : "+f"(c[0]), "+f"(c[1]), "+f"(c[2]), "+f"(c[3])
                 : "r"(a[0]), "r"(a[1]), "r"(a[2]), "r"(a[3]), "r"(b0), "r"(b1));
}

// ---------------- prep: split fp32 -> bf16 hi/lo + row norms ----------------
__global__ void prep_r(const float* __restrict__ src) {
    __shared__ float part[8];
    long long row = blockIdx.x * 2 + (threadIdx.x >> 7);
    int t = threadIdx.x & 127;
    float4 v = *(const float4*)(src + row * D + t * 4);
    __nv_bfloat16 hx = __float2bfloat16(v.x), hy = __float2bfloat16(v.y);
    __nv_bfloat16 hz = __float2bfloat16(v.z), hw = __float2bfloat16(v.w);
    __nv_bfloat16 lx = __float2bfloat16(v.x - __bfloat162float(hx));
    __nv_bfloat16 ly = __float2bfloat16(v.y - __bfloat162float(hy));
    __nv_bfloat16 lz = __float2bfloat16(v.z - __bfloat162float(hz));
    __nv_bfloat16 lw = __float2bfloat16(v.w - __bfloat162float(hw));
    long long o = row * D + t * 4;
    ((__nv_bfloat162*)(g_Rhi + o))[0] = __nv_bfloat162{hx, hy};
    ((__nv_bfloat162*)(g_Rhi + o))[1] = __nv_bfloat162{hz, hw};
    ((__nv_bfloat162*)(g_Rlo + o))[0] = __nv_bfloat162{lx, ly};
    ((__nv_bfloat162*)(g_Rlo + o))[1] = __nv_bfloat162{lz, lw};
    float s = v.x * v.x + v.y * v.y + v.z * v.z + v.w * v.w;
    #pragma unroll
    for (int k = 16; k; k >>= 1) s += __shfl_xor_sync(0xffffffffu, s, k);
    if ((threadIdx.x & 31) == 0) part[threadIdx.x >> 5] = s;
    __syncthreads();
    if (t == 0) {
        int b = (threadIdx.x >> 7) * 4;
        g_z2[row] = part[b] + part[b + 1] + part[b + 2] + part[b + 3];
    }
}

__global__ void prep_e(const float* __restrict__ src) {
    __shared__ float part[8];
    if (blockIdx.x == 0 && threadIdx.x == 0) g_loss_acc = 0.0;
    long long row = blockIdx.x * 2 + (threadIdx.x >> 7);
    int t = threadIdx.x & 127;
    float4 v = *(const float4*)(src + row * D + t * 4);
    __nv_bfloat16 hx = __float2bfloat16(v.x), hy = __float2bfloat16(v.y);
    __nv_bfloat16 hz = __float2bfloat16(v.z), hw = __float2bfloat16(v.w);
    __nv_bfloat16 lx = __float2bfloat16(v.x - __bfloat162float(hx));
    __nv_bfloat16 ly = __float2bfloat16(v.y - __bfloat162float(hy));
    __nv_bfloat16 lz = __float2bfloat16(v.z - __bfloat162float(hz));
    __nv_bfloat16 lw = __float2bfloat16(v.w - __bfloat162float(hw));
    long long o = row * D + t * 4;
    ((__nv_bfloat162*)(g_Ehi + o))[0] = __nv_bfloat162{hx, hy};
    ((__nv_bfloat162*)(g_Ehi + o))[1] = __nv_bfloat162{hz, hw};
    ((__nv_bfloat162*)(g_Elo + o))[0] = __nv_bfloat162{lx, ly};
    ((__nv_bfloat162*)(g_Elo + o))[1] = __nv_bfloat162{lz, lw};
    float s = v.x * v.x + v.y * v.y + v.z * v.z + v.w * v.w;
    #pragma unroll
    for (int k = 16; k; k >>= 1) s += __shfl_xor_sync(0xffffffffu, s, k);
    if ((threadIdx.x & 31) == 0) part[threadIdx.x >> 5] = s;
    __syncthreads();
    if (t == 0) {
        int b = (threadIdx.x >> 7) * 4;
        g_e2[row] = part[b] + part[b + 1] + part[b + 2] + part[b + 3];
    }
}

// ---------------- main: mma.sync bf16x3 GEMM + fused VQ epilogue ------------
// stage: A (128 rows x [32k hi | 32k lo] = 128B) 16KB | B same 16KB = 32KB
// 3-stage ring = 96KB dynamic smem; 2 CTAs / SM; B frags loaded per-ng to
// keep the live register set < 128 (no spill at launch_bounds(256,2)).
constexpr int STAGE = 32768;
constexpr int DSMEM = 3 * STAGE;
constexpr int KC_PER_NC = D / BK;          // 16
constexpr int ITERS = (NCODES / BN) * KC_PER_NC;  // 128

__global__ void __launch_bounds__(256, 2) vq_main(const float* __restrict__ resid,
                                                  const float* __restrict__ emb,
                                                  float* __restrict__ out) {
    extern __shared__ char dsm[];
    __shared__ float z2s[BM];
    __shared__ float e2sh[NCODES];
    __shared__ float bestV[BM][2];
    __shared__ int   bestI[BM][2];
    __shared__ int   sidx[BM];
    __shared__ float wsum[8];

    const int tid = threadIdx.x, wid = tid >> 5, lane = tid & 31;
    const int warp_m = wid & 3, warp_n = wid >> 2;
    const long long row0 = (long long)blockIdx.x * BM;
    const u32 sbase = smem_u32(dsm);

    if (tid < BM) z2s[tid] = g_z2[row0 + tid];
    for (int i = tid; i < NCODES; i += 256) e2sh[i] = g_e2[i];

    float bv[4]; int bi[4];
    #pragma unroll
    for (int s = 0; s < 4; ++s) { bv[s] = 3.4e38f; bi[s] = 0; }

    // load mapping (constant per thread): sub = tid&7 selects hi(0-3)/lo(4-7)
    const int sub  = tid & 7;
    const int rbase = tid >> 3;                    // 0..31
    const bool is_hi = sub < 4;
    const int koff8 = (sub & 3) * 8;               // bf16 elements within 32-k chunk
    const u32 dsub = (u32)(sub * 16);              // byte offset in 128B row

    const __nv_bfloat16* Asrc = is_hi ? g_Rhi : g_Rlo;
    const __nv_bfloat16* Bsrc = is_hi ? g_Ehi : g_Elo;

    // ---- pipeline prologue: stages for it=0,1 ----
    #pragma unroll
    for (int p = 0; p < 2; ++p) {
        const int nc2 = p >> 4, kc2 = p & 15;
        u32 st = sbase + (u32)((p % 3) * STAGE);
        #pragma unroll
        for (int i = 0; i < 4; ++i) {
            int r = rbase + i * 32;
            u32 off = SW128((u32)(r * 128) + dsub);
            CP16(st + off,         Asrc + (row0 + r) * D + kc2 * BK + koff8);
            CP16(st + 16384 + off, Bsrc + (long long)(nc2 * BN + r) * D + kc2 * BK + koff8);
        }
        CP_COMMIT();
    }

    float acc[2][8][4];

    for (int it = 0; it < ITERS; ++it) {
        const int nc = it >> 4, kc = it & 15;
        if (kc == 0) {
            #pragma unroll
            for (int mt = 0; mt < 2; ++mt)
                #pragma unroll
                for (int nt = 0; nt < 8; ++nt)
                    #pragma unroll
                    for (int q = 0; q < 4; ++q) acc[mt][nt][q] = 0.f;
        }
        // prefetch it+2
        if (it + 2 < ITERS) {
            const int j = it + 2, nc2 = j >> 4, kc2 = j & 15;
            u32 st = sbase + (u32)((j % 3) * STAGE);
            #pragma unroll
            for (int i = 0; i < 4; ++i) {
                int r = rbase + i * 32;
                u32 off = SW128((u32)(r * 128) + dsub);
                CP16(st + off,         Asrc + (row0 + r) * D + kc2 * BK + koff8);
                CP16(st + 16384 + off, Bsrc + (long long)(nc2 * BN + r) * D + kc2 * BK + koff8);
            }
        }
        CP_COMMIT();
        CP_WAIT2();
        __syncthreads();

        const u32 Ab = sbase + (u32)((it % 3) * STAGE);
        const u32 Bb = Ab + 16384;

        #pragma unroll
        for (int ks = 0; ks < 2; ++ks) {
            const u32 kb = (u32)(ks * 32 + ((lane >> 4) << 4));
            // A fragments: 16 regs live
            u32 a_hi[2][4], a_lo[2][4];
            #pragma unroll
            for (int mt = 0; mt < 2; ++mt) {
                u32 rowoff = (u32)((warp_m * 32 + mt * 16 + (lane & 15)) << 7);
                ldsm4(a_hi[mt], Ab + SW128(rowoff + kb));
                ldsm4(a_lo[mt], Ab + SW128(rowoff + kb + 64));
            }
            // B fragments: one ng group at a time (8 regs live)
            #pragma unroll
            for (int ng = 0; ng < 4; ++ng) {
                u32 b_hi[4], b_lo[4];
                u32 rowoff = (u32)((warp_n * 64 + ng * 16 + (lane & 15)) << 7);
                ldsm4(b_hi, Bb + SW128(rowoff + kb));
                ldsm4(b_lo, Bb + SW128(rowoff + kb + 64));
                #pragma unroll
                for (int mt = 0; mt < 2; ++mt)
                    #pragma unroll
                    for (int sb = 0; sb < 2; ++sb) {
                        float* c = acc[mt][ng * 2 + sb];
                        mma16816(c, a_hi[mt], b_hi[sb], b_hi[sb + 2]); // hh
                        mma16816(c, a_hi[mt], b_lo[sb], b_lo[sb + 2]); // hl
                        mma16816(c, a_lo[mt], b_hi[sb], b_hi[sb + 2]); // lh
                    }
            }
        }

        if (kc == 15) {
            // ---- epilogue: dist, argmin, store (regs + read-only smem) ----
            const int qr = lane >> 2, qc = lane & 3;
            #pragma unroll
            for (int mt = 0; mt < 2; ++mt) {
                const int ra = warp_m * 32 + mt * 16 + qr;
                const int rb = ra + 8;
                const float z2a = z2s[ra], z2b = z2s[rb];
                #pragma unroll
                for (int nt = 0; nt < 8; ++nt) {
                    const int col = nc * BN + warp_n * 64 + nt * 8 + qc * 2;
                    const float e0 = e2sh[col], e1 = e2sh[col + 1];
                    float d00 = fmaf(-2.f, acc[mt][nt][0], z2a + e0);
                    float d01 = fmaf(-2.f, acc[mt][nt][1], z2a + e1);
                    float d10 = fmaf(-2.f, acc[mt][nt][2], z2b + e0);
                    float d11 = fmaf(-2.f, acc[mt][nt][3], z2b + e1);
                    const int sa = mt * 2, sbs = mt * 2 + 1;
                    if (d00 < bv[sa])  { bv[sa] = d00;  bi[sa] = col; }
                    if (d01 < bv[sa])  { bv[sa] = d01;  bi[sa] = col + 1; }
                    if (d10 < bv[sbs]) { bv[sbs] = d10; bi[sbs] = col; }
                    if (d11 < bv[sbs]) { bv[sbs] = d11; bi[sbs] = col + 1; }
                    long long oa = DIST_OFF + (row0 + ra) * 1024 + col;
                    long long ob = DIST_OFF + (row0 + rb) * 1024 + col;
                    out[oa] = d00; out[oa + 1] = d01;
                    out[ob] = d10; out[ob + 1] = d11;
                }
            }
        }
        __syncthreads();
    }

    // ---- per-row argmin reduce (quad shfl, then across warp_n halves) ----
    #pragma unroll
    for (int s = 0; s < 4; ++s) {
        #pragma unroll
        for (int o = 1; o <= 2; o <<= 1) {
            float vv = __shfl_xor_sync(0xffffffffu, bv[s], o);
            int   ii = __shfl_xor_sync(0xffffffffu, bi[s], o);
            if (vv < bv[s] || (vv == bv[s] && ii < bi[s])) { bv[s] = vv; bi[s] = ii; }
        }
    }
    if ((lane & 3) == 0) {
        const int qr = lane >> 2;
        #pragma unroll
        for (int mt = 0; mt < 2; ++mt) {
            int ra = warp_m * 32 + mt * 16 + qr;
            bestV[ra][warp_n] = bv[mt * 2];     bestI[ra][warp_n] = bi[mt * 2];
            bestV[ra + 8][warp_n] = bv[mt * 2 + 1]; bestI[ra + 8][warp_n] = bi[mt * 2 + 1];
        }
    }
    __syncthreads();
    if (tid < BM) {
        float v0 = bestV[tid][0]; int i0 = bestI[tid][0];
        float v1 = bestV[tid][1]; int i1 = bestI[tid][1];
        bool t1 = (v1 < v0) || (v1 == v0 && i1 < i0);
        int b = t1 ? i1 : i0;
        sidx[tid] = b;
        out[IDX_OFF + row0 + tid] = (float)b;
    }
    __syncthreads();

    // ---- z_st gather + loss partial (exact fp32 from original inputs) ----
    float lsum = 0.f;
    for (int base = tid * 4; base < BM * D; base += 256 * 4) {
        int r = base >> 9;
        int d = base & (D - 1);
        int ci = sidx[r];
        float4 q = *(const float4*)&emb[(long long)ci * D + d];
        long long g = (row0 + r) * D + d;
        float4 rv = *(const float4*)&resid[g];
        *(float4*)&out[Z_OFF + g] = q;
        float d0 = q.x - rv.x, d1 = q.y - rv.y, d2 = q.z - rv.z, d3 = q.w - rv.w;
        lsum += d0 * d0 + d1 * d1 + d2 * d2 + d3 * d3;
    }
    #pragma unroll
    for (int o = 16; o; o >>= 1) lsum += __shfl_xor_sync(0xffffffffu, lsum, o);
    if (lane == 0) wsum[wid] = lsum;
    __syncthreads();
    if (tid == 0) {
        float s = 0.f;
        #pragma unroll
        for (int w = 0; w < 8; ++w) s += wsum[w];
        atomicAdd(&g_loss_acc, (double)s);
    }
}

__global__ void finalize_kernel(float* __restrict__ out) {
    out[LOSS_OFF] = (float)(1.25 * g_loss_acc / 16777216.0);
}

extern "C" void kernel_launch(void* const* d_in, const int* in_sizes, int n_in,
                              void* d_out, int out_size) {
    const float* resid = (const float*)d_in[0];
    const float* emb   = (const float*)d_in[1];
    if (n_in >= 2 && in_sizes[0] == 524288 && in_sizes[1] == 16777216) {
        const float* t = resid; resid = emb; emb = t;
    }
    float* out = (float*)d_out;

    static int smem_set = 0;
    if (!smem_set) {
        cudaFuncSetAttribute(vq_main, cudaFuncAttributeMaxDynamicSharedMemorySize, DSMEM);
        smem_set = 1;
    }

    prep_r<<<16384, 256>>>(resid);
    prep_e<<<512, 256>>>(emb);
    vq_main<<<256, 256, DSMEM>>>(resid, emb, out);
    finalize_kernel<<<1, 1>>>(out);
}

// round 7
// speedup vs baseline: 2.8932x; 1.1847x over previous
#include <cuda_runtime.h>
#include <cuda_bf16.h>
#include <cstdint>

typedef unsigned long long u64;
typedef unsigned int u32;

// ---------------- problem constants ----------------
constexpr int D = 512, NCODES = 1024;
constexpr long long NBT = 32768;
constexpr long long Z_OFF = 0, LOSS_OFF = 16777216, DIST_OFF = 16777217, IDX_OFF = 50331649;

constexpr int BM = 128;      // rows per CTA
constexpr int BN = 128;      // codes per n-chunk
constexpr int BK = 32;       // bf16 k per chunk; tile row = [hi 64B | lo 64B] = 128B

constexpr int TILE = 16384;          // 128 rows x 128B, pre-swizzled
constexpr int STAGE = 2 * TILE;      // A tile + B tile
constexpr int DSMEM = 3 * STAGE + 1024;
constexpr int KC_PER_NC = D / BK;                  // 16
constexpr int ITERS = (NCODES / BN) * KC_PER_NC;   // 128

// ---------------- device scratch (tile-major, pre-swizzled) ----------------
__device__ __align__(128) unsigned char g_Rt[(NBT / BM) * KC_PER_NC * TILE]; // 64MB
__device__ __align__(128) unsigned char g_Et[(NCODES / BM) * KC_PER_NC * TILE]; // 2MB
__device__ float  g_z2[NBT];
__device__ float  g_e2[NCODES];
__device__ double g_loss_acc;

// ---------------- PTX helpers (all sm_90-baseline: safe for compute_103) ---
__device__ __forceinline__ u32 smem_u32(const void* p) {
    u32 a;
    asm("{ .reg .u64 t; cvta.to.shared.u64 t, %1; cvt.u32.u64 %0, t; }" : "=r"(a) : "l"(p));
    return a;
}
#define SW128(o) ((o) ^ (((o) >> 3) & 0x70))

#define MBAR_INIT(a, c) asm volatile("mbarrier.init.shared.b64 [%0], %1;" :: "r"(a), "r"(c) : "memory")
#define MBAR_EXPECT_TX(a, b) \
    asm volatile("mbarrier.arrive.expect_tx.shared.b64 _, [%0], %1;" :: "r"(a), "r"(b) : "memory")
#define MBAR_WAIT(a, ph) do {                                                          \
    u32 _a = (a), _p = (u32)(ph), _d;                                                  \
    asm volatile("{ .reg .pred p; mbarrier.try_wait.parity.acquire.cta.shared::cta.b64 p, [%1], %2; selp.b32 %0,1,0,p; }" \
                 : "=r"(_d) : "r"(_a), "r"(_p) : "memory");                            \
    if (!_d) {                                                                         \
        asm volatile("{ .reg .pred P1; WL%=: mbarrier.try_wait.parity.acquire.cta.shared::cta.b64 P1, [%0], %1, 0x989680;" \
                     " @P1 bra.uni WD%=; bra.uni WL%=; WD%=: }" :: "r"(_a), "r"(_p) : "memory"); \
    } } while (0)
#define BULK_G2S(dst, src, bytes, mbar)                                                \
    asm volatile("cp.async.bulk.shared::cluster.global.mbarrier::complete_tx::bytes "  \
                 "[%0], [%1], %2, [%3];"                                               \
                 :: "r"(dst), "l"(src), "r"(bytes), "r"(mbar) : "memory")
#define FENCE_ASYNC() asm volatile("fence.proxy.async.shared::cta;" ::: "memory")

__device__ __forceinline__ void ldsm4(u32* r, u32 addr) {
    asm volatile("ldmatrix.sync.aligned.m8n8.x4.shared.b16 {%0,%1,%2,%3}, [%4];"
                 : "=r"(r[0]), "=r"(r[1]), "=r"(r[2]), "=r"(r[3]) : "r"(addr));
}
__device__ __forceinline__ void mma16816(float* c, const u32* a, u32 b0, u32 b1) {
    asm volatile("mma.sync.aligned.m16n8k16.row.col.f32.bf16.bf16.f32 "
                 "{%0,%1,%2,%3}, {%4,%5,%6,%7}, {%8,%9}, {%0,%1,%2,%3};"
                 : "+f"(c[0]), "+f"(c[1]), "+f"(c[2]), "+f"(c[3])
                 : "r"(a[0]), "r"(a[1]), "r"(a[2]), "r"(a[3]), "r"(b0), "r"(b1));
}

// ---------------- prep: split fp32 -> bf16 hi/lo tiles + row norms ----------
// One block = 2 rows (128 threads/row); thread t owns k = 4t..4t+3.
// Destination: tile (blk = row>>7, kc = t>>3); within tile the 128B row is
// [hi 64B | lo 64B], SW128-swizzled — identical to the smem image vq_main uses.
__device__ __forceinline__ void split_row(const float* __restrict__ src,
                                          unsigned char* __restrict__ dst_tiles,
                                          long long row, int t) {
    float4 v = *(const float4*)(src + row * D + t * 4);
    __nv_bfloat16 hx = __float2bfloat16(v.x), hy = __float2bfloat16(v.y);
    __nv_bfloat16 hz = __float2bfloat16(v.z), hw = __float2bfloat16(v.w);
    __nv_bfloat16 lx = __float2bfloat16(v.x - __bfloat162float(hx));
    __nv_bfloat16 ly = __float2bfloat16(v.y - __bfloat162float(hy));
    __nv_bfloat16 lz = __float2bfloat16(v.z - __bfloat162float(hz));
    __nv_bfloat16 lw = __float2bfloat16(v.w - __bfloat162float(hw));
    u32 h01, h23, l01, l23;
    {
        __nv_bfloat162 a{hx, hy}, b{hz, hw}, c{lx, ly}, d{lz, lw};
        h01 = *(u32*)&a; h23 = *(u32*)&b; l01 = *(u32*)&c; l23 = *(u32*)&d;
    }
    const int blk = (int)(row >> 7), m = (int)(row & 127);
    const int kc = t >> 3, c0 = (t & 7) * 4;
    unsigned char* tile = dst_tiles + ((size_t)blk * KC_PER_NC + kc) * TILE;
    u32 off_hi = SW128((u32)(m * 128 + c0 * 2));
    u32 off_lo = SW128((u32)(m * 128 + 64 + c0 * 2));
    *(u64*)(tile + off_hi) = (u64)h01 | ((u64)h23 << 32);
    *(u64*)(tile + off_lo) = (u64)l01 | ((u64)l23 << 32);
}

__global__ void prep_r(const float* __restrict__ src) {
    __shared__ float part[8];
    long long row = blockIdx.x * 2 + (threadIdx.x >> 7);
    int t = threadIdx.x & 127;
    float4 v = *(const float4*)(src + row * D + t * 4);
    split_row(src, g_Rt, row, t);
    float s = v.x * v.x + v.y * v.y + v.z * v.z + v.w * v.w;
    #pragma unroll
    for (int k = 16; k; k >>= 1) s += __shfl_xor_sync(0xffffffffu, s, k);
    if ((threadIdx.x & 31) == 0) part[threadIdx.x >> 5] = s;
    __syncthreads();
    if (t == 0) {
        int b = (threadIdx.x >> 7) * 4;
        g_z2[row] = part[b] + part[b + 1] + part[b + 2] + part[b + 3];
    }
}

__global__ void prep_e(const float* __restrict__ src) {
    __shared__ float part[8];
    if (blockIdx.x == 0 && threadIdx.x == 0) g_loss_acc = 0.0;
    long long row = blockIdx.x * 2 + (threadIdx.x >> 7);
    int t = threadIdx.x & 127;
    float4 v = *(const float4*)(src + row * D + t * 4);
    split_row(src, g_Et, row, t);
    float s = v.x * v.x + v.y * v.y + v.z * v.z + v.w * v.w;
    #pragma unroll
    for (int k = 16; k; k >>= 1) s += __shfl_xor_sync(0xffffffffu, s, k);
    if ((threadIdx.x & 31) == 0) part[threadIdx.x >> 5] = s;
    __syncthreads();
    if (t == 0) {
        int b = (threadIdx.x >> 7) * 4;
        g_e2[row] = part[b] + part[b + 1] + part[b + 2] + part[b + 3];
    }
}

// ---------------- main: bulk-TMA-fed mma.sync bf16x3 GEMM + fused epilogue --
__global__ void __launch_bounds__(256, 2) vq_main(const float* __restrict__ resid,
                                                  const float* __restrict__ emb,
                                                  float* __restrict__ out) {
    extern __shared__ char dsm[];
    __shared__ __align__(8) u64 s_full[3];
    __shared__ float z2s[BM];
    __shared__ float e2sh[NCODES];
    __shared__ float bestV[BM][2];
    __shared__ int   bestI[BM][2];
    __shared__ int   sidx[BM];
    __shared__ float wsum[8];

    const int tid = threadIdx.x, wid = tid >> 5, lane = tid & 31;
    const int warp_m = wid & 3, warp_n = wid >> 2;
    const long long row0 = (long long)blockIdx.x * BM;

    u32 dyn = smem_u32(dsm);
    const u32 sbase = (dyn + 1023) & ~1023u;   // 1KB-align the tile ring

    if (tid == 0) {
        MBAR_INIT(smem_u32(&s_full[0]), 1);
        MBAR_INIT(smem_u32(&s_full[1]), 1);
        MBAR_INIT(smem_u32(&s_full[2]), 1);
        FENCE_ASYNC();
    }
    if (tid < BM) z2s[tid] = g_z2[row0 + tid];
    for (int i = tid; i < NCODES; i += 256) e2sh[i] = g_e2[i];
    __syncthreads();

    const unsigned char* Abase = g_Rt + (size_t)blockIdx.x * KC_PER_NC * TILE;

    // preload stages for it = 0, 1
    if (tid == 0) {
        #pragma unroll
        for (int p = 0; p < 2; ++p) {
            const int nc2 = p >> 4, kc2 = p & 15;
            u32 mb = smem_u32(&s_full[p]);
            u32 st = sbase + (u32)(p * STAGE);
            MBAR_EXPECT_TX(mb, (u32)STAGE);
            BULK_G2S(st,        Abase + (size_t)kc2 * TILE, (u32)TILE, mb);
            BULK_G2S(st + TILE, g_Et + ((size_t)nc2 * KC_PER_NC + kc2) * TILE, (u32)TILE, mb);
        }
    }

    float bv[4]; int bi[4];
    #pragma unroll
    for (int s = 0; s < 4; ++s) { bv[s] = 3.4e38f; bi[s] = 0; }

    float acc[2][8][4];

    for (int it = 0; it < ITERS; ++it) {
        const int nc = it >> 4, kc = it & 15;
        if (kc == 0) {
            #pragma unroll
            for (int mt = 0; mt < 2; ++mt)
                #pragma unroll
                for (int nt = 0; nt < 8; ++nt)
                    #pragma unroll
                    for (int q = 0; q < 4; ++q) acc[mt][nt][q] = 0.f;
        }
        // prefetch it+2 into stage (it+2)%3 (freed by the sync at end of it-1)
        if (tid == 0 && it + 2 < ITERS) {
            const int j = it + 2, nc2 = j >> 4, kc2 = j & 15;
            u32 mb = smem_u32(&s_full[j % 3]);
            u32 st = sbase + (u32)((j % 3) * STAGE);
            MBAR_EXPECT_TX(mb, (u32)STAGE);
            BULK_G2S(st,        Abase + (size_t)kc2 * TILE, (u32)TILE, mb);
            BULK_G2S(st + TILE, g_Et + ((size_t)nc2 * KC_PER_NC + kc2) * TILE, (u32)TILE, mb);
        }
        // wait current stage
        MBAR_WAIT(smem_u32(&s_full[it % 3]), (it / 3) & 1);

        const u32 Ab = sbase + (u32)((it % 3) * STAGE);
        const u32 Bb = Ab + TILE;

        #pragma unroll
        for (int ks = 0; ks < 2; ++ks) {
            const u32 kb = (u32)(ks * 32 + ((lane >> 4) << 4));
            u32 a_hi[2][4], a_lo[2][4];
            #pragma unroll
            for (int mt = 0; mt < 2; ++mt) {
                u32 rowoff = (u32)((warp_m * 32 + mt * 16 + (lane & 15)) << 7);
                ldsm4(a_hi[mt], Ab + SW128(rowoff + kb));
                ldsm4(a_lo[mt], Ab + SW128(rowoff + kb + 64));
            }
            #pragma unroll
            for (int ng = 0; ng < 4; ++ng) {
                u32 b_hi[4], b_lo[4];
                u32 rowoff = (u32)((warp_n * 64 + ng * 16 + (lane & 15)) << 7);
                ldsm4(b_hi, Bb + SW128(rowoff + kb));
                ldsm4(b_lo, Bb + SW128(rowoff + kb + 64));
                #pragma unroll
                for (int mt = 0; mt < 2; ++mt)
                    #pragma unroll
                    for (int sb = 0; sb < 2; ++sb) {
                        float* c = acc[mt][ng * 2 + sb];
                        mma16816(c, a_hi[mt], b_hi[sb], b_hi[sb + 2]); // hh
                        mma16816(c, a_hi[mt], b_lo[sb], b_lo[sb + 2]); // hl
                        mma16816(c, a_lo[mt], b_hi[sb], b_hi[sb + 2]); // lh
                    }
            }
        }

        if (kc == 15) {
            // ---- epilogue: dist, argmin, store ----
            const int qr = lane >> 2, qc = lane & 3;
            #pragma unroll
            for (int mt = 0; mt < 2; ++mt) {
                const int ra = warp_m * 32 + mt * 16 + qr;
                const int rb = ra + 8;
                const float z2a = z2s[ra], z2b = z2s[rb];
                #pragma unroll
                for (int nt = 0; nt < 8; ++nt) {
                    const int col = nc * BN + warp_n * 64 + nt * 8 + qc * 2;
                    const float e0 = e2sh[col], e1 = e2sh[col + 1];
                    float d00 = fmaf(-2.f, acc[mt][nt][0], z2a + e0);
                    float d01 = fmaf(-2.f, acc[mt][nt][1], z2a + e1);
                    float d10 = fmaf(-2.f, acc[mt][nt][2], z2b + e0);
                    float d11 = fmaf(-2.f, acc[mt][nt][3], z2b + e1);
                    const int sa = mt * 2, sbs = mt * 2 + 1;
                    if (d00 < bv[sa])  { bv[sa] = d00;  bi[sa] = col; }
                    if (d01 < bv[sa])  { bv[sa] = d01;  bi[sa] = col + 1; }
                    if (d10 < bv[sbs]) { bv[sbs] = d10; bi[sbs] = col; }
                    if (d11 < bv[sbs]) { bv[sbs] = d11; bi[sbs] = col + 1; }
                    long long oa = DIST_OFF + (row0 + ra) * 1024 + col;
                    long long ob = DIST_OFF + (row0 + rb) * 1024 + col;
                    out[oa] = d00; out[oa + 1] = d01;
                    out[ob] = d10; out[ob + 1] = d11;
                }
            }
        }
        __syncthreads();
    }

    // ---- per-row argmin reduce ----
    #pragma unroll
    for (int s = 0; s < 4; ++s) {
        #pragma unroll
        for (int o = 1; o <= 2; o <<= 1) {
            float vv = __shfl_xor_sync(0xffffffffu, bv[s], o);
            int   ii = __shfl_xor_sync(0xffffffffu, bi[s], o);
            if (vv < bv[s] || (vv == bv[s] && ii < bi[s])) { bv[s] = vv; bi[s] = ii; }
        }
    }
    if ((lane & 3) == 0) {
        const int qr = lane >> 2;
        #pragma unroll
        for (int mt = 0; mt < 2; ++mt) {
            int ra = warp_m * 32 + mt * 16 + qr;
            bestV[ra][warp_n] = bv[mt * 2];     bestI[ra][warp_n] = bi[mt * 2];
            bestV[ra + 8][warp_n] = bv[mt * 2 + 1]; bestI[ra + 8][warp_n] = bi[mt * 2 + 1];
        }
    }
    __syncthreads();
    if (tid < BM) {
        float v0 = bestV[tid][0]; int i0 = bestI[tid][0];
        float v1 = bestV[tid][1]; int i1 = bestI[tid][1];
        bool t1 = (v1 < v0) || (v1 == v0 && i1 < i0);
        int b = t1 ? i1 : i0;
        sidx[tid] = b;
        out[IDX_OFF + row0 + tid] = (float)b;
    }
    __syncthreads();

    // ---- z_st gather + loss partial (exact fp32 from original inputs) ----
    float lsum = 0.f;
    for (int base = tid * 4; base < BM * D; base += 256 * 4) {
        int r = base >> 9;
        int d = base & (D - 1);
        int ci = sidx[r];
        float4 q = *(const float4*)&emb[(long long)ci * D + d];
        long long g = (row0 + r) * D + d;
        float4 rv = *(const float4*)&resid[g];
        *(float4*)&out[Z_OFF + g] = q;
        float d0 = q.x - rv.x, d1 = q.y - rv.y, d2 = q.z - rv.z, d3 = q.w - rv.w;
        lsum += d0 * d0 + d1 * d1 + d2 * d2 + d3 * d3;
    }
    #pragma unroll
    for (int o = 16; o; o >>= 1) lsum += __shfl_xor_sync(0xffffffffu, lsum, o);
    if (lane == 0) wsum[wid] = lsum;
    __syncthreads();
    if (tid == 0) {
        float s = 0.f;
        #pragma unroll
        for (int w = 0; w < 8; ++w) s += wsum[w];
        atomicAdd(&g_loss_acc, (double)s);
    }
}

__global__ void finalize_kernel(float* __restrict__ out) {
    out[LOSS_OFF] = (float)(1.25 * g_loss_acc / 16777216.0);
}

extern "C" void kernel_launch(void* const* d_in, const int* in_sizes, int n_in,
                              void* d_out, int out_size) {
    const float* resid = (const float*)d_in[0];
    const float* emb   = (const float*)d_in[1];
    if (n_in >= 2 && in_sizes[0] == 524288 && in_sizes[1] == 16777216) {
        const float* t = resid; resid = emb; emb = t;
    }
    float* out = (float*)d_out;

    static int smem_set = 0;
    if (!smem_set) {
        cudaFuncSetAttribute(vq_main, cudaFuncAttributeMaxDynamicSharedMemorySize, DSMEM);
        smem_set = 1;
    }

    prep_r<<<16384, 256>>>(resid);
    prep_e<<<512, 256>>>(emb);
    vq_main<<<256, 256, DSMEM>>>(resid, emb, out);
    finalize_kernel<<<1, 1>>>(out);
}

// round 8
// speedup vs baseline: 5.0302x; 1.7386x over previous
#include <cuda_runtime.h>
#include <cuda_bf16.h>
#include <cstdint>

typedef unsigned long long u64;
typedef unsigned int u32;

// ---------------- problem constants ----------------
constexpr int D = 512, NCODES = 1024;
constexpr long long NBT = 32768;
constexpr long long Z_OFF = 0, LOSS_OFF = 16777216, DIST_OFF = 16777217, IDX_OFF = 50331649;

constexpr int BM = 128;      // rows per CTA
constexpr int BN = 128;      // codes per n-chunk
constexpr int BK = 64;       // bf16 k per chunk = 128B tile rows (hi only)

constexpr int TILE = 16384;          // 128 rows x 128B, pre-swizzled bf16-hi
constexpr int STAGE = 2 * TILE;      // A tile + B tile = 32KB
constexpr int DSMEM = 3 * STAGE + 1024;
constexpr int KC_PER_NC = D / BK;                  // 8
constexpr int ITERS = (NCODES / BN) * KC_PER_NC;   // 64

constexpr float TAU = 0.1f;          // refine candidate threshold (>>2x max bf16 dot err)

// ---------------- device scratch (tile-major, pre-swizzled) ----------------
__device__ __align__(128) unsigned char g_Rt[(NBT / BM) * KC_PER_NC * TILE];    // 32MB
__device__ __align__(128) unsigned char g_Et[(NCODES / BM) * KC_PER_NC * TILE]; // 1MB
__device__ float  g_z2[NBT];
__device__ float  g_e2[NCODES];
__device__ double g_loss_acc;

// ---------------- PTX helpers (sm_90-baseline: safe for compute_103) -------
__device__ __forceinline__ u32 smem_u32(const void* p) {
    u32 a;
    asm("{ .reg .u64 t; cvta.to.shared.u64 t, %1; cvt.u32.u64 %0, t; }" : "=r"(a) : "l"(p));
    return a;
}
#define SW128(o) ((o) ^ (((o) >> 3) & 0x70))

#define MBAR_INIT(a, c) asm volatile("mbarrier.init.shared.b64 [%0], %1;" :: "r"(a), "r"(c) : "memory")
#define MBAR_EXPECT_TX(a, b) \
    asm volatile("mbarrier.arrive.expect_tx.shared.b64 _, [%0], %1;" :: "r"(a), "r"(b) : "memory")
#define MBAR_WAIT(a, ph) do {                                                          \
    u32 _a = (a), _p = (u32)(ph), _d;                                                  \
    asm volatile("{ .reg .pred p; mbarrier.try_wait.parity.acquire.cta.shared::cta.b64 p, [%1], %2; selp.b32 %0,1,0,p; }" \
                 : "=r"(_d) : "r"(_a), "r"(_p) : "memory");                            \
    if (!_d) {                                                                         \
        asm volatile("{ .reg .pred P1; WL%=: mbarrier.try_wait.parity.acquire.cta.shared::cta.b64 P1, [%0], %1, 0x989680;" \
                     " @P1 bra.uni WD%=; bra.uni WL%=; WD%=: }" :: "r"(_a), "r"(_p) : "memory"); \
    } } while (0)
#define BULK_G2S(dst, src, bytes, mbar)                                                \
    asm volatile("cp.async.bulk.shared::cluster.global.mbarrier::complete_tx::bytes "  \
                 "[%0], [%1], %2, [%3];"                                               \
                 :: "r"(dst), "l"(src), "r"(bytes), "r"(mbar) : "memory")
#define FENCE_ASYNC() asm volatile("fence.proxy.async.shared::cta;" ::: "memory")

__device__ __forceinline__ void ldsm4(u32* r, u32 addr) {
    asm volatile("ldmatrix.sync.aligned.m8n8.x4.shared.b16 {%0,%1,%2,%3}, [%4];"
                 : "=r"(r[0]), "=r"(r[1]), "=r"(r[2]), "=r"(r[3]) : "r"(addr));
}
__device__ __forceinline__ void mma16816(float* c, const u32* a, u32 b0, u32 b1) {
    asm volatile("mma.sync.aligned.m16n8k16.row.col.f32.bf16.bf16.f32 "
                 "{%0,%1,%2,%3}, {%4,%5,%6,%7}, {%8,%9}, {%0,%1,%2,%3};"
                 : "+f"(c[0]), "+f"(c[1]), "+f"(c[2]), "+f"(c[3])
                 : "r"(a[0]), "r"(a[1]), "r"(a[2]), "r"(a[3]), "r"(b0), "r"(b1));
}

// ---------------- prep: fp32 -> bf16-hi tiles + exact row norms -------------
// Block = 2 rows (128 threads/row); thread t owns k = 4t..4t+3.
// Tile (blk=row>>7, kc=t>>4): 128B row (64 bf16), SW128-swizzled.
__device__ __forceinline__ void split_row(const float* __restrict__ src,
                                          unsigned char* __restrict__ dst_tiles,
                                          long long row, int t) {
    float4 v = *(const float4*)(src + row * D + t * 4);
    __nv_bfloat162 h01{__float2bfloat16(v.x), __float2bfloat16(v.y)};
    __nv_bfloat162 h23{__float2bfloat16(v.z), __float2bfloat16(v.w)};
    const int blk = (int)(row >> 7), m = (int)(row & 127);
    const int kc = t >> 4, c0 = (t & 15) * 4;
    unsigned char* tile = dst_tiles + ((size_t)blk * KC_PER_NC + kc) * TILE;
    u32 off = SW128((u32)(m * 128 + c0 * 2));
    *(u64*)(tile + off) = (u64)(*(u32*)&h01) | ((u64)(*(u32*)&h23) << 32);
}

__global__ void prep_r(const float* __restrict__ src) {
    __shared__ float part[8];
    long long row = blockIdx.x * 2 + (threadIdx.x >> 7);
    int t = threadIdx.x & 127;
    float4 v = *(const float4*)(src + row * D + t * 4);
    split_row(src, g_Rt, row, t);
    float s = v.x * v.x + v.y * v.y + v.z * v.z + v.w * v.w;
    #pragma unroll
    for (int k = 16; k; k >>= 1) s += __shfl_xor_sync(0xffffffffu, s, k);
    if ((threadIdx.x & 31) == 0) part[threadIdx.x >> 5] = s;
    __syncthreads();
    if (t == 0) {
        int b = (threadIdx.x >> 7) * 4;
        g_z2[row] = part[b] + part[b + 1] + part[b + 2] + part[b + 3];
    }
}

__global__ void prep_e(const float* __restrict__ src) {
    __shared__ float part[8];
    if (blockIdx.x == 0 && threadIdx.x == 0) g_loss_acc = 0.0;
    long long row = blockIdx.x * 2 + (threadIdx.x >> 7);
    int t = threadIdx.x & 127;
    float4 v = *(const float4*)(src + row * D + t * 4);
    split_row(src, g_Et, row, t);
    float s = v.x * v.x + v.y * v.y + v.z * v.z + v.w * v.w;
    #pragma unroll
    for (int k = 16; k; k >>= 1) s += __shfl_xor_sync(0xffffffffu, s, k);
    if ((threadIdx.x & 31) == 0) part[threadIdx.x >> 5] = s;
    __syncthreads();
    if (t == 0) {
        int b = (threadIdx.x >> 7) * 4;
        g_e2[row] = part[b] + part[b + 1] + part[b + 2] + part[b + 3];
    }
}

// ---------------- main: bulk-TMA-fed single-product bf16 GEMM, dist only ----
__global__ void __launch_bounds__(256, 2) vq_main(float* __restrict__ out) {
    extern __shared__ char dsm[];
    __shared__ __align__(8) u64 s_full[3];
    __shared__ float z2s[BM];
    __shared__ float e2sh[NCODES];

    const int tid = threadIdx.x, wid = tid >> 5, lane = tid & 31;
    const int warp_m = wid & 3, warp_n = wid >> 2;
    const long long row0 = (long long)blockIdx.x * BM;

    u32 dyn = smem_u32(dsm);
    const u32 sbase = (dyn + 1023) & ~1023u;

    if (tid == 0) {
        MBAR_INIT(smem_u32(&s_full[0]), 1);
        MBAR_INIT(smem_u32(&s_full[1]), 1);
        MBAR_INIT(smem_u32(&s_full[2]), 1);
        FENCE_ASYNC();
    }
    if (tid < BM) z2s[tid] = g_z2[row0 + tid];
    for (int i = tid; i < NCODES; i += 256) e2sh[i] = g_e2[i];
    __syncthreads();

    const unsigned char* Abase = g_Rt + (size_t)blockIdx.x * KC_PER_NC * TILE;

    if (tid == 0) {
        #pragma unroll
        for (int p = 0; p < 2; ++p) {
            const int nc2 = p >> 3, kc2 = p & 7;
            u32 mb = smem_u32(&s_full[p]);
            u32 st = sbase + (u32)(p * STAGE);
            MBAR_EXPECT_TX(mb, (u32)STAGE);
            BULK_G2S(st,        Abase + (size_t)kc2 * TILE, (u32)TILE, mb);
            BULK_G2S(st + TILE, g_Et + ((size_t)nc2 * KC_PER_NC + kc2) * TILE, (u32)TILE, mb);
        }
    }

    float acc[2][8][4];

    for (int it = 0; it < ITERS; ++it) {
        const int nc = it >> 3, kc = it & 7;
        if (kc == 0) {
            #pragma unroll
            for (int mt = 0; mt < 2; ++mt)
                #pragma unroll
                for (int nt = 0; nt < 8; ++nt)
                    #pragma unroll
                    for (int q = 0; q < 4; ++q) acc[mt][nt][q] = 0.f;
        }
        if (tid == 0 && it + 2 < ITERS) {
            const int j = it + 2, nc2 = j >> 3, kc2 = j & 7;
            u32 mb = smem_u32(&s_full[j % 3]);
            u32 st = sbase + (u32)((j % 3) * STAGE);
            MBAR_EXPECT_TX(mb, (u32)STAGE);
            BULK_G2S(st,        Abase + (size_t)kc2 * TILE, (u32)TILE, mb);
            BULK_G2S(st + TILE, g_Et + ((size_t)nc2 * KC_PER_NC + kc2) * TILE, (u32)TILE, mb);
        }
        MBAR_WAIT(smem_u32(&s_full[it % 3]), (it / 3) & 1);

        const u32 Ab = sbase + (u32)((it % 3) * STAGE);
        const u32 Bb = Ab + TILE;

        #pragma unroll
        for (int ks = 0; ks < 4; ++ks) {
            const u32 kb = (u32)((ks * 2 + (lane >> 4)) << 4);
            u32 a[2][4];
            #pragma unroll
            for (int mt = 0; mt < 2; ++mt) {
                u32 rowoff = (u32)((warp_m * 32 + mt * 16 + (lane & 15)) << 7);
                ldsm4(a[mt], Ab + SW128(rowoff + kb));
            }
            #pragma unroll
            for (int ng = 0; ng < 4; ++ng) {
                u32 b[4];
                u32 rowoff = (u32)((warp_n * 64 + ng * 16 + (lane & 15)) << 7);
                ldsm4(b, Bb + SW128(rowoff + kb));
                #pragma unroll
                for (int mt = 0; mt < 2; ++mt)
                    #pragma unroll
                    for (int sb = 0; sb < 2; ++sb)
                        mma16816(acc[mt][ng * 2 + sb], a[mt], b[sb], b[sb + 2]);
            }
        }

        if (kc == 7) {
            // dist = z2 + e2 - 2*dot, store (argmin handled by refine kernel)
            const int qr = lane >> 2, qc = lane & 3;
            #pragma unroll
            for (int mt = 0; mt < 2; ++mt) {
                const int ra = warp_m * 32 + mt * 16 + qr;
                const int rb = ra + 8;
                const float z2a = z2s[ra], z2b = z2s[rb];
                #pragma unroll
                for (int nt = 0; nt < 8; ++nt) {
                    const int col = nc * BN + warp_n * 64 + nt * 8 + qc * 2;
                    const float e0 = e2sh[col], e1 = e2sh[col + 1];
                    long long oa = DIST_OFF + (row0 + ra) * 1024 + col;
                    long long ob = DIST_OFF + (row0 + rb) * 1024 + col;
                    out[oa]     = fmaf(-2.f, acc[mt][nt][0], z2a + e0);
                    out[oa + 1] = fmaf(-2.f, acc[mt][nt][1], z2a + e1);
                    out[ob]     = fmaf(-2.f, acc[mt][nt][2], z2b + e0);
                    out[ob + 1] = fmaf(-2.f, acc[mt][nt][3], z2b + e1);
                }
            }
        }
        __syncthreads();
    }
}

// ---------------- refine: exact argmin + idx + z_st gather + loss -----------
// One warp per row. Cheap-dist min; codes within TAU get exact fp32 recompute.
__global__ void __launch_bounds__(256) refine(const float* __restrict__ resid,
                                              const float* __restrict__ emb,
                                              float* __restrict__ out) {
    __shared__ float wls[8];
    const int wid = threadIdx.x >> 5, lane = threadIdx.x & 31;
    const long long row = (long long)blockIdx.x * 8 + wid;

    const float* drow = out + DIST_OFF + row * 1024;
    float vals[32];
    float bv = 3.4e38f; int bi = 0;
    #pragma unroll
    for (int j = 0; j < 32; ++j) {
        float v = drow[j * 32 + lane];
        vals[j] = v;
        int c = j * 32 + lane;
        if (v < bv || (v == bv && c < bi)) { bv = v; bi = c; }
    }
    #pragma unroll
    for (int o = 16; o; o >>= 1) {
        float vv = __shfl_xor_sync(0xffffffffu, bv, o);
        int   ii = __shfl_xor_sync(0xffffffffu, bi, o);
        if (vv < bv || (vv == bv && ii < bi)) { bv = vv; bi = ii; }
    }

    const float thr = bv + TAU;
    u32 mymask = 0; int cnt = 0;
    #pragma unroll
    for (int j = 0; j < 32; ++j)
        if (vals[j] < thr) { mymask |= 1u << j; ++cnt; }
    #pragma unroll
    for (int o = 16; o; o >>= 1) cnt += __shfl_xor_sync(0xffffffffu, cnt, o);

    int finali = bi;
    if (cnt > 1) {
        const float* rp = resid + row * D;
        float bestd = 3.4e38f; int besti = 1 << 30;
        for (int j = 0; j < 32; ++j) {
            u32 bal = __ballot_sync(0xffffffffu, (mymask >> j) & 1u);
            while (bal) {
                int src = __ffs(bal) - 1;
                bal &= bal - 1;
                int c = j * 32 + src;
                const float* ep = emb + (long long)c * D;
                float part = 0.f;
                #pragma unroll
                for (int q = 0; q < 4; ++q) {
                    int i4 = (q * 32 + lane) * 4;
                    float4 rv = *(const float4*)(rp + i4);
                    float4 ev = *(const float4*)(ep + i4);
                    part += rv.x * ev.x + rv.y * ev.y + rv.z * ev.z + rv.w * ev.w;
                }
                #pragma unroll
                for (int o = 16; o; o >>= 1) part += __shfl_xor_sync(0xffffffffu, part, o);
                float dex = fmaf(-2.f, part, g_z2[row] + g_e2[c]);
                if (dex < bestd || (dex == bestd && c < besti)) { bestd = dex; besti = c; }
            }
        }
        finali = besti;
    }

    if (lane == 0) out[IDX_OFF + row] = (float)finali;

    // z_st = emb[finali]; loss partial
    const float* ep = emb + (long long)finali * D;
    const float* rp = resid + row * D;
    float lsum = 0.f;
    #pragma unroll
    for (int q = 0; q < 4; ++q) {
        int i4 = (q * 32 + lane) * 4;
        float4 qv = *(const float4*)(ep + i4);
        float4 rv = *(const float4*)(rp + i4);
        *(float4*)(out + Z_OFF + row * D + i4) = qv;
        float d0 = qv.x - rv.x, d1 = qv.y - rv.y, d2 = qv.z - rv.z, d3 = qv.w - rv.w;
        lsum += d0 * d0 + d1 * d1 + d2 * d2 + d3 * d3;
    }
    #pragma unroll
    for (int o = 16; o; o >>= 1) lsum += __shfl_xor_sync(0xffffffffu, lsum, o);
    if (lane == 0) wls[wid] = lsum;
    __syncthreads();
    if (threadIdx.x == 0) {
        float s = 0.f;
        #pragma unroll
        for (int w = 0; w < 8; ++w) s += wls[w];
        atomicAdd(&g_loss_acc, (double)s);
    }
}

__global__ void finalize_kernel(float* __restrict__ out) {
    out[LOSS_OFF] = (float)(1.25 * g_loss_acc / 16777216.0);
}

extern "C" void kernel_launch(void* const* d_in, const int* in_sizes, int n_in,
                              void* d_out, int out_size) {
    const float* resid = (const float*)d_in[0];
    const float* emb   = (const float*)d_in[1];
    if (n_in >= 2 && in_sizes[0] == 524288 && in_sizes[1] == 16777216) {
        const float* t = resid; resid = emb; emb = t;
    }
    float* out = (float*)d_out;

    static int smem_set = 0;
    if (!smem_set) {
        cudaFuncSetAttribute(vq_main, cudaFuncAttributeMaxDynamicSharedMemorySize, DSMEM);
        smem_set = 1;
    }

    prep_r<<<16384, 256>>>(resid);
    prep_e<<<512, 256>>>(emb);
    vq_main<<<256, 256, DSMEM>>>(out);
    refine<<<4096, 256>>>(resid, emb, out);
    finalize_kernel<<<1, 1>>>(out);
}